// round 5
// baseline (speedup 1.0000x reference)
#include <cuda_runtime.h>
#include <cuda_bf16.h>
#include <stdint.h>

// FineMatching R5: ldmatrix + mma.sync (bf16 hi/lo split, 3 passes) GEMM for conf,
// register-resident D-frag softmax, smem Ef aliased over A tiles, lazy conf_ff epilogue.
// (tcgen05 path is unreachable: harness emits compute_103 base PTX.)

#define TPB 128
#define SE 68     // Ef stride [r][l] floats
#define SAF 68    // Aff stride floats
#define SBF 113   // Bff stride floats

// byte offsets in dynamic smem
#define B_AHI   0        // feat1 hi bf16 [112 r][72], 16128 B (rows 100..111 uninit, never read as conf)
#define B_ALO   16128    // feat1 lo
#define B_BHI   32256    // feat0 hi bf16 [64 l][72], 9216 B
#define B_BLO   41472
#define B_EF    0        // Ef [100][68] f32 = 27200 B, aliases A tiles (dead after GEMM)
#define B_AFF   50688    // 8*68*4  = 2176
#define B_BFF   52864    // 8*113*4 = 3616
#define B_IROW  56480    // 64 f32
#define B_ICOL  56736    // 100 f32
#define B_RED   57136    // 16 f32
#define SMEM_BYTES 57216 // <= 58368 -> 4 CTAs/SM

#define ASTRIDE_B 144    // 72 bf16 per row: 4-bank shift/row -> conflict-free ldmatrix

__device__ __forceinline__ uint32_t smem_u32(const void* p) {
    uint32_t a;
    asm("{ .reg .u64 t; cvta.to.shared.u64 t, %1; cvt.u32.u64 %0, t; }"
        : "=r"(a) : "l"(p));
    return a;
}
__device__ __forceinline__ void ldm4(uint32_t addr, uint32_t* r) {
    asm volatile("ldmatrix.sync.aligned.m8n8.x4.shared.b16 {%0,%1,%2,%3}, [%4];"
                 : "=r"(r[0]), "=r"(r[1]), "=r"(r[2]), "=r"(r[3]) : "r"(addr));
}
__device__ __forceinline__ void mma16816(float* d, const uint32_t* a, uint32_t b0, uint32_t b1) {
    asm volatile("mma.sync.aligned.m16n8k16.row.col.f32.bf16.bf16.f32 "
                 "{%0,%1,%2,%3}, {%4,%5,%6,%7}, {%8,%9}, {%0,%1,%2,%3};"
                 : "+f"(d[0]), "+f"(d[1]), "+f"(d[2]), "+f"(d[3])
                 : "r"(a[0]), "r"(a[1]), "r"(a[2]), "r"(a[3]), "r"(b0), "r"(b1));
}
__device__ __forceinline__ uint32_t pack_bf2(__nv_bfloat16 a, __nv_bfloat16 b) {
    __nv_bfloat162 t = __halves2bfloat162(a, b);
    return *reinterpret_cast<uint32_t*>(&t);
}
// split (x,y) into packed bf16 hi pair + lo (residual) pair
__device__ __forceinline__ void split2(float x, float y, uint32_t& hi, uint32_t& lo) {
    __nv_bfloat16 hx = __float2bfloat16(x), hy = __float2bfloat16(y);
    __nv_bfloat16 lx = __float2bfloat16(x - __bfloat162float(hx));
    __nv_bfloat16 ly = __float2bfloat16(y - __bfloat162float(hy));
    hi = pack_bf2(hx, hy);
    lo = pack_bf2(lx, ly);
}

// one GEMM pass: acc += A(pass) @ B(pass)^T over K=64 (4 k16 steps)
__device__ __forceinline__ void gemm_pass(uint32_t Aa, uint32_t Ba,
                                          float acc[2][8][4], bool two_m) {
    #pragma unroll
    for (int ks = 0; ks < 4; ks++) {
        uint32_t a0[4], a1[4];
        ldm4(Aa + ks * 32, a0);
        if (two_m) ldm4(Aa + 16 * ASTRIDE_B + ks * 32, a1);
        #pragma unroll
        for (int j2 = 0; j2 < 4; j2++) {
            uint32_t b[4];
            ldm4(Ba + j2 * 16 * ASTRIDE_B + ks * 32, b);
            mma16816(acc[0][2 * j2],     a0, b[0], b[1]);
            mma16816(acc[0][2 * j2 + 1], a0, b[2], b[3]);
            if (two_m) {
                mma16816(acc[1][2 * j2],     a1, b[0], b[1]);
                mma16816(acc[1][2 * j2 + 1], a1, b[2], b[3]);
            }
        }
    }
}

__global__ __launch_bounds__(TPB, 4)
void fine_matching_kernel(const float* __restrict__ feat0,
                          const float* __restrict__ feat1,
                          const float* __restrict__ mk0c,
                          const float* __restrict__ mk1c,
                          const int*   __restrict__ hw0i,
                          const int*   __restrict__ hw0f,
                          float* __restrict__ out_mk0,
                          float* __restrict__ out_mk1,
                          float* __restrict__ out_probs,
                          float* __restrict__ out_sm)
{
    extern __shared__ float smem[];
    uint8_t* smb = reinterpret_cast<uint8_t*>(smem);
    const uint32_t sb = smem_u32(smem);

    float* Ef     = reinterpret_cast<float*>(smb + B_EF);
    float* Aff    = reinterpret_cast<float*>(smb + B_AFF);
    float* Bff    = reinterpret_cast<float*>(smb + B_BFF);
    float* invRow = reinterpret_cast<float*>(smb + B_IROW);
    float* invCol = reinterpret_cast<float*>(smb + B_ICOL);
    float* red    = reinterpret_cast<float*>(smb + B_RED);

    const int m    = blockIdx.x;
    const int tid  = threadIdx.x;
    const int wid  = tid >> 5;
    const int lane = tid & 31;

    // ---------------- load: fp32 -> bf16 hi/lo tiles + ff side buffers ----------------
    {
        const float4* f1 = reinterpret_cast<const float4*>(feat1 + (size_t)m * 6400);
        #pragma unroll 4
        for (int idx = tid; idx < 1600; idx += TPB) {
            float4 v = f1[idx];
            int r = idx >> 4, c4 = (idx & 15) << 2;
            if (c4 < 56) {
                uint32_t h01, l01, h23, l23;
                split2(v.x, v.y, h01, l01);
                split2(v.z, v.w, h23, l23);
                uint32_t off = (uint32_t)r * ASTRIDE_B + c4 * 2;
                *reinterpret_cast<uint2*>(smb + B_AHI + off) = make_uint2(h01, h23);
                *reinterpret_cast<uint2*>(smb + B_ALO + off) = make_uint2(l01, l23);
            } else {
                uint32_t off = (uint32_t)r * ASTRIDE_B + c4 * 2;
                *reinterpret_cast<uint2*>(smb + B_AHI + off) = make_uint2(0u, 0u);
                *reinterpret_cast<uint2*>(smb + B_ALO + off) = make_uint2(0u, 0u);
                int c = c4 - 56;
                Bff[(c + 0) * SBF + r] = v.x;
                Bff[(c + 1) * SBF + r] = v.y;
                Bff[(c + 2) * SBF + r] = v.z;
                Bff[(c + 3) * SBF + r] = v.w;
            }
        }
        const float4* f0 = reinterpret_cast<const float4*>(feat0 + (size_t)m * 4096);
        #pragma unroll 4
        for (int idx = tid; idx < 1024; idx += TPB) {
            float4 v = f0[idx];
            int l = idx >> 4, c4 = (idx & 15) << 2;
            if (c4 < 56) {
                uint32_t h01, l01, h23, l23;
                split2(v.x, v.y, h01, l01);
                split2(v.z, v.w, h23, l23);
                uint32_t off = (uint32_t)l * ASTRIDE_B + c4 * 2;
                *reinterpret_cast<uint2*>(smb + B_BHI + off) = make_uint2(h01, h23);
                *reinterpret_cast<uint2*>(smb + B_BLO + off) = make_uint2(l01, l23);
            } else {
                uint32_t off = (uint32_t)l * ASTRIDE_B + c4 * 2;
                *reinterpret_cast<uint2*>(smb + B_BHI + off) = make_uint2(0u, 0u);
                *reinterpret_cast<uint2*>(smb + B_BLO + off) = make_uint2(0u, 0u);
                int c = c4 - 56;
                Aff[(c + 0) * SAF + l] = v.x;
                Aff[(c + 1) * SAF + l] = v.y;
                Aff[(c + 2) * SAF + l] = v.z;
                Aff[(c + 3) * SAF + l] = v.w;
            }
        }
        // A rows 100..111 left uninitialized: their conf rows are never read.
    }
    __syncthreads();

    // ---------------- GEMM: conf[r][l] = feat1 . feat0^T (c<56), hi/lo 3 passes ----------------
    const bool two_m = (wid < 3);
    // ldmatrix lane address offsets
    const uint32_t aLane = (uint32_t)(lane & 15) * ASTRIDE_B + (uint32_t)(lane >> 4) * 16;
    const uint32_t bLane = (uint32_t)(((lane >> 4) & 1) * 8 + (lane & 7)) * ASTRIDE_B
                         + (uint32_t)((lane >> 3) & 1) * 16;
    const uint32_t mOff  = (uint32_t)wid * 32 * ASTRIDE_B;

    float acc[2][8][4];
    #pragma unroll
    for (int t = 0; t < 2; t++)
        #pragma unroll
        for (int n = 0; n < 8; n++)
            #pragma unroll
            for (int q = 0; q < 4; q++) acc[t][n][q] = 0.0f;

    gemm_pass(sb + B_AHI + mOff + aLane, sb + B_BHI + bLane, acc, two_m);  // hi*hi
    gemm_pass(sb + B_AHI + mOff + aLane, sb + B_BLO + bLane, acc, two_m);  // hi*lo
    gemm_pass(sb + B_ALO + mOff + aLane, sb + B_BHI + bLane, acc, two_m);  // lo*hi

    // D frag rows: t-tile rows ra = 32w+16t+(lane>>2), rb = ra+8; cols 8n+2(lane&3)(+1)
    const int tmax = two_m ? 2 : 1;

    // ---------------- gmax (guard r<100) ----------------
    float lmax = -3.0e38f;
    #pragma unroll
    for (int t = 0; t < 2; t++) {
        if (t >= tmax) break;
        int ra = 32 * wid + 16 * t + (lane >> 2);
        int rb = ra + 8;
        #pragma unroll
        for (int n = 0; n < 8; n++) {
            if (ra < 100) lmax = fmaxf(lmax, fmaxf(acc[t][n][0], acc[t][n][1]));
            if (rb < 100) lmax = fmaxf(lmax, fmaxf(acc[t][n][2], acc[t][n][3]));
        }
    }
    #pragma unroll
    for (int off = 16; off; off >>= 1)
        lmax = fmaxf(lmax, __shfl_xor_sync(0xffffffffu, lmax, off));
    if (lane == 0) red[wid] = lmax;
    __syncthreads();   // all warps past GEMM -> Ef alias over A is now safe
    if (tid == 0)
        red[8] = fmaxf(fmaxf(red[0], red[1]), fmaxf(red[2], red[3])) * (1.0f / 64.0f);
    __syncthreads();
    const float gmax = red[8];

    // ---------------- exp, Ef stores, invCol (per-r sum over l) ----------------
    const float inv64 = 1.0f / 64.0f;
    #pragma unroll
    for (int t = 0; t < 2; t++) {
        if (t >= tmax) break;
        int ra = 32 * wid + 16 * t + (lane >> 2);
        int rb = ra + 8;
        int cbase = 2 * (lane & 3);
        float sa = 0.0f, sbm = 0.0f;
        #pragma unroll
        for (int n = 0; n < 8; n++) {
            float e0 = __expf(fmaf(acc[t][n][0], inv64, -gmax));
            float e1 = __expf(fmaf(acc[t][n][1], inv64, -gmax));
            float e2 = __expf(fmaf(acc[t][n][2], inv64, -gmax));
            float e3 = __expf(fmaf(acc[t][n][3], inv64, -gmax));
            int c = 8 * n + cbase;
            if (ra < 100) {
                *reinterpret_cast<float2*>(&Ef[ra * SE + c]) = make_float2(e0, e1);
                sa += e0 + e1;
            }
            if (rb < 100) {
                *reinterpret_cast<float2*>(&Ef[rb * SE + c]) = make_float2(e2, e3);
                sbm += e2 + e3;
            }
        }
        sa  += __shfl_xor_sync(0xffffffffu, sa, 1);
        sa  += __shfl_xor_sync(0xffffffffu, sa, 2);
        sbm += __shfl_xor_sync(0xffffffffu, sbm, 1);
        sbm += __shfl_xor_sync(0xffffffffu, sbm, 2);
        if ((lane & 3) == 0) {
            if (ra < 100) invCol[ra] = 1.0f / sa;
            if (rb < 100) invCol[rb] = 1.0f / sbm;
        }
    }
    __syncthreads();

    // invRow[l] = 1 / sum_{r<100} Ef[r][l]   (lanes read consecutive l: conflict-free)
    if (tid < 64) {
        float s = 0.0f;
        #pragma unroll 4
        for (int rr = 0; rr < 100; rr++) s += Ef[rr * SE + tid];
        invRow[tid] = 1.0f / s;
    }
    __syncthreads();

    // ---------------- sm output + argmax (first-index tie-break) ----------------
    float best = -1.0f;
    int   bidx = 0;
    float* smo = out_sm + (size_t)m * 4096;
    #pragma unroll
    for (int f = tid; f < 4096; f += TPB) {
        int l = f >> 6, k = f & 63;
        int rr = 11 + ((k >> 3) * 10) + (k & 7);  // inner crop of 10x10
        float e = Ef[rr * SE + l];
        float v = e * e * invRow[l] * invCol[rr];
        smo[f] = v;
        if (v > best) { best = v; bidx = f; }
    }
    #pragma unroll
    for (int off = 16; off; off >>= 1) {
        float ov = __shfl_xor_sync(0xffffffffu, best, off);
        int   oi = __shfl_xor_sync(0xffffffffu, bidx, off);
        if (ov > best || (ov == best && oi < bidx)) { best = ov; bidx = oi; }
    }
    if (lane == 0) {
        red[4 + wid] = best;
        reinterpret_cast<int*>(red)[8 + wid] = bidx;
    }
    __syncthreads();
    if (tid == 0) {
        float bv = red[4];
        int   bi = reinterpret_cast<int*>(red)[8];
        #pragma unroll
        for (int w2 = 1; w2 < 4; w2++) {
            float ov = red[4 + w2];
            int   oi = reinterpret_cast<int*>(red)[8 + w2];
            if (ov > bv || (ov == bv && oi < bi)) { bv = ov; bi = oi; }
        }
        reinterpret_cast<int*>(red)[12] = bi;
    }
    __syncthreads();
    const int idx = reinterpret_cast<int*>(red)[12];

    // ---------------- epilogue: lazy conf_ff window + softmax + keypoints ----------------
    if (tid < 32) {
        const int idx_l = idx >> 6;
        const int idx_r = idx & 63;
        const float scl = (float)(*hw0i) / (float)(*hw0f);
        const float rs8 = 0.35355339059327376f;  // 1/sqrt(8)

        const int  di = tid / 3;
        const int  dj = tid - di * 3;
        const bool vv = tid < 9;

        float w = -3.0e38f;
        if (vv) {
            int wi = (idx_r >> 3) + di - 1; if (wi < 0) wi += 10;
            int wj = (idx_r & 7)  + dj - 1; if (wj < 0) wj += 10;
            int wr = wi * 10 + wj;
            float dot = 0.0f;
            #pragma unroll
            for (int c = 0; c < 8; c++)
                dot = fmaf(Aff[c * SAF + idx_l], Bff[c * SBF + wr], dot);
            w = dot * rs8;
        }
        float mx = w;
        #pragma unroll
        for (int off = 16; off; off >>= 1)
            mx = fmaxf(mx, __shfl_xor_sync(0xffffffffu, mx, off));
        float t = vv ? __expf((w - mx) * 0.1f) : 0.0f;   // TEMP = 10
        float s = t;
        #pragma unroll
        for (int off = 16; off; off >>= 1)
            s += __shfl_xor_sync(0xffffffffu, s, off);
        float pr = t / s;
        if (vv) out_probs[(size_t)m * 9 + tid] = pr;

        float cx = vv ? pr * (float)(dj - 1) : 0.0f;
        float cy = vv ? pr * (float)(di - 1) : 0.0f;
        #pragma unroll
        for (int off = 16; off; off >>= 1) {
            cx += __shfl_xor_sync(0xffffffffu, cx, off);
            cy += __shfl_xor_sync(0xffffffffu, cy, off);
        }
        if (tid == 0) {
            float m0x = mk0c[2 * m], m0y = mk0c[2 * m + 1];
            float m1x = mk1c[2 * m], m1y = mk1c[2 * m + 1];
            out_mk0[2 * m]     = fmaf((float)(idx_l & 7) - 3.5f, scl, m0x);
            out_mk0[2 * m + 1] = fmaf((float)(idx_l >> 3) - 3.5f, scl, m0y);
            out_mk1[2 * m]     = m1x + ((float)(idx_r & 7) - 3.5f) * scl + cx * scl;
            out_mk1[2 * m + 1] = m1y + ((float)(idx_r >> 3) - 3.5f) * scl + cy * scl;
        }
    }
}

extern "C" void kernel_launch(void* const* d_in, const int* in_sizes, int n_in,
                              void* d_out, int out_size) {
    const float* feat0 = (const float*)d_in[0];
    const float* feat1 = (const float*)d_in[1];
    const float* mk0c  = (const float*)d_in[2];
    const float* mk1c  = (const float*)d_in[3];
    // d_in[4] = mconf (unused), d_in[5] = b_ids (unused)
    const int* hw0i = (const int*)d_in[6];
    const int* hw0f = (const int*)d_in[7];

    const int M = in_sizes[0] / 4096;

    float* out       = (float*)d_out;
    float* out_mk0   = out;
    float* out_mk1   = out + (size_t)2 * M;
    float* out_probs = out + (size_t)4 * M;
    float* out_sm    = out + (size_t)13 * M;

    cudaFuncSetAttribute(fine_matching_kernel,
                         cudaFuncAttributeMaxDynamicSharedMemorySize, SMEM_BYTES);
    fine_matching_kernel<<<M, TPB, SMEM_BYTES>>>(
        feat0, feat1, mk0c, mk1c, hw0i, hw0f,
        out_mk0, out_mk1, out_probs, out_sm);
}

// round 6
// speedup vs baseline: 1.1331x; 1.1331x over previous
#include <cuda_runtime.h>
#include <cuda_bf16.h>
#include <stdint.h>

// FineMatching R6: A (feat1) loaded gmem->registers directly into mma fragments;
// B (feat0) staged once as bf16 hi/lo in smem for ldmatrix; 3-pass bf16 hi/lo GEMM
// (hh+hl+lh) on mma.sync; 256 threads (8 warps x 16 rows); smem 32.9KB -> 24 warps/SM.

#define TPB 256
#define SE 66     // Ef stride [r][l] floats
#define SAF 68    // Aff stride floats
#define SBF 113   // Bff stride floats
#define BSTR 144  // feat0 bf16 tile row stride bytes (72 b16)

// byte offsets in dynamic smem
#define B_AFF   0        // 8*68*4  = 2176   (feat0 ch 56..63, [c][l])
#define B_BFF   2176     // 8*113*4 = 3616   (feat1 ch 56..63, [c][r])
#define B_BHI   5792     // feat0 hi bf16 [64 l][72], 9216
#define B_BLO   15008    // feat0 lo bf16, 9216 -> 24224
#define B_EF    5792     // Ef [100][66] f32 = 26400, aliases B tiles (dead after GEMM) -> 32192
#define B_IROW  32192    // 64 f32
#define B_ICOL  32448    // 100 f32
#define B_RED   32848    // 20 f32 (floats 0..8 gmax, ints 8..16 argmax)
#define SMEM_BYTES 32928

__device__ __forceinline__ uint32_t smem_u32(const void* p) {
    uint32_t a;
    asm("{ .reg .u64 t; cvta.to.shared.u64 t, %1; cvt.u32.u64 %0, t; }"
        : "=r"(a) : "l"(p));
    return a;
}
__device__ __forceinline__ void ldm4(uint32_t addr, uint32_t* r) {
    asm volatile("ldmatrix.sync.aligned.m8n8.x4.shared.b16 {%0,%1,%2,%3}, [%4];"
                 : "=r"(r[0]), "=r"(r[1]), "=r"(r[2]), "=r"(r[3]) : "r"(addr));
}
__device__ __forceinline__ void mma16816(float* d, const uint32_t* a, uint32_t b0, uint32_t b1) {
    asm volatile("mma.sync.aligned.m16n8k16.row.col.f32.bf16.bf16.f32 "
                 "{%0,%1,%2,%3}, {%4,%5,%6,%7}, {%8,%9}, {%0,%1,%2,%3};"
                 : "+f"(d[0]), "+f"(d[1]), "+f"(d[2]), "+f"(d[3])
                 : "r"(a[0]), "r"(a[1]), "r"(a[2]), "r"(a[3]), "r"(b0), "r"(b1));
}
__device__ __forceinline__ uint32_t pack_bf2(__nv_bfloat16 a, __nv_bfloat16 b) {
    __nv_bfloat162 t = __halves2bfloat162(a, b);
    return *reinterpret_cast<uint32_t*>(&t);
}
__device__ __forceinline__ void split2(float x, float y, uint32_t& hi, uint32_t& lo) {
    __nv_bfloat16 hx = __float2bfloat16(x), hy = __float2bfloat16(y);
    __nv_bfloat16 lx = __float2bfloat16(x - __bfloat162float(hx));
    __nv_bfloat16 ly = __float2bfloat16(y - __bfloat162float(hy));
    hi = pack_bf2(hx, hy);
    lo = pack_bf2(lx, ly);
}

__global__ __launch_bounds__(TPB, 3)
void fine_matching_kernel(const float* __restrict__ feat0,
                          const float* __restrict__ feat1,
                          const float* __restrict__ mk0c,
                          const float* __restrict__ mk1c,
                          const int*   __restrict__ hw0i,
                          const int*   __restrict__ hw0f,
                          float* __restrict__ out_mk0,
                          float* __restrict__ out_mk1,
                          float* __restrict__ out_probs,
                          float* __restrict__ out_sm)
{
    extern __shared__ float smem[];
    uint8_t* smb = reinterpret_cast<uint8_t*>(smem);
    const uint32_t sb = smem_u32(smem);

    float* Ef     = reinterpret_cast<float*>(smb + B_EF);
    float* Aff    = reinterpret_cast<float*>(smb + B_AFF);
    float* Bff    = reinterpret_cast<float*>(smb + B_BFF);
    float* invRow = reinterpret_cast<float*>(smb + B_IROW);
    float* invCol = reinterpret_cast<float*>(smb + B_ICOL);
    float* red    = reinterpret_cast<float*>(smb + B_RED);
    int*   ired   = reinterpret_cast<int*>(red);

    const int m    = blockIdx.x;
    const int tid  = threadIdx.x;
    const int wid  = tid >> 5;
    const int lane = tid & 31;
    const int q    = lane >> 2;
    const int c2   = lane & 3;

    // ---------------- stage feat0 -> bf16 hi/lo tiles (+ Aff ch 56..63) ----------------
    {
        const float4* f0 = reinterpret_cast<const float4*>(feat0 + (size_t)m * 4096);
        #pragma unroll 2
        for (int idx = tid; idx < 1024; idx += TPB) {
            float4 v = f0[idx];
            int l = idx >> 4, c4 = (idx & 15) << 2;
            uint32_t off = (uint32_t)l * BSTR + c4 * 2;
            if (c4 < 56) {
                uint32_t h01, l01, h23, l23;
                split2(v.x, v.y, h01, l01);
                split2(v.z, v.w, h23, l23);
                *reinterpret_cast<uint2*>(smb + B_BHI + off) = make_uint2(h01, h23);
                *reinterpret_cast<uint2*>(smb + B_BLO + off) = make_uint2(l01, l23);
            } else {
                *reinterpret_cast<uint2*>(smb + B_BHI + off) = make_uint2(0u, 0u);
                *reinterpret_cast<uint2*>(smb + B_BLO + off) = make_uint2(0u, 0u);
                int c = c4 - 56;
                Aff[(c + 0) * SAF + l] = v.x;
                Aff[(c + 1) * SAF + l] = v.y;
                Aff[(c + 2) * SAF + l] = v.z;
                Aff[(c + 3) * SAF + l] = v.w;
            }
        }
    }

    // ---------------- preload feat1 fragments gmem->regs (warps 0..6), harvest Bff ----------------
    const int  r0 = 16 * wid + q;      // warp's A rows: r0, r0+8
    const bool v0 = (wid < 7) && (r0 < 100);
    const bool v1 = (wid < 7) && (r0 + 8 < 100);
    float2 af[4][4];
    if (wid < 7) {
        const float* A = feat1 + (size_t)m * 6400;
        const float2 z = make_float2(0.0f, 0.0f);
        #pragma unroll
        for (int ks = 0; ks < 4; ks++) {
            int k0 = 16 * ks + 2 * c2;
            af[ks][0] = v0 ? *reinterpret_cast<const float2*>(A + r0 * 64 + k0) : z;
            af[ks][1] = v1 ? *reinterpret_cast<const float2*>(A + (r0 + 8) * 64 + k0) : z;
            if (ks < 3) {
                af[ks][2] = v0 ? *reinterpret_cast<const float2*>(A + r0 * 64 + k0 + 8) : z;
                af[ks][3] = v1 ? *reinterpret_cast<const float2*>(A + (r0 + 8) * 64 + k0 + 8) : z;
            } else {
                af[ks][2] = z;
                af[ks][3] = z;
            }
        }
        // ff channels 56+2c2, 57+2c2 of rows r0, r0+8 -> Bff
        float2 w0 = v0 ? *reinterpret_cast<const float2*>(A + r0 * 64 + 56 + 2 * c2) : z;
        float2 w1 = v1 ? *reinterpret_cast<const float2*>(A + (r0 + 8) * 64 + 56 + 2 * c2) : z;
        if (v0) {
            Bff[(2 * c2 + 0) * SBF + r0] = w0.x;
            Bff[(2 * c2 + 1) * SBF + r0] = w0.y;
        }
        if (v1) {
            Bff[(2 * c2 + 0) * SBF + r0 + 8] = w1.x;
            Bff[(2 * c2 + 1) * SBF + r0 + 8] = w1.y;
        }
    }
    __syncthreads();

    // ---------------- GEMM: 3 bf16 terms (hh + hl + lh) fused per k-step ----------------
    float acc[8][4];
    #pragma unroll
    for (int n = 0; n < 8; n++)
        #pragma unroll
        for (int p = 0; p < 4; p++) acc[n][p] = 0.0f;

    if (wid < 7) {
        const uint32_t bLane = (uint32_t)((((lane >> 4) & 1) * 8 + (lane & 7)) * BSTR)
                             + (uint32_t)(((lane >> 3) & 1) * 16);
        const uint32_t Bh = sb + B_BHI + bLane;
        const uint32_t Bl = sb + B_BLO + bLane;
        #pragma unroll
        for (int ks = 0; ks < 4; ks++) {
            uint32_t ah[4], al[4];
            #pragma unroll
            for (int i = 0; i < 4; i++)
                split2(af[ks][i].x, af[ks][i].y, ah[i], al[i]);
            #pragma unroll
            for (int j2 = 0; j2 < 4; j2++) {
                uint32_t bh[4], bl[4];
                ldm4(Bh + j2 * 16 * BSTR + ks * 32, bh);
                ldm4(Bl + j2 * 16 * BSTR + ks * 32, bl);
                mma16816(acc[2 * j2],     ah, bh[0], bh[1]);
                mma16816(acc[2 * j2 + 1], ah, bh[2], bh[3]);
                mma16816(acc[2 * j2],     ah, bl[0], bl[1]);
                mma16816(acc[2 * j2 + 1], ah, bl[2], bl[3]);
                mma16816(acc[2 * j2],     al, bh[0], bh[1]);
                mma16816(acc[2 * j2 + 1], al, bh[2], bh[3]);
            }
        }
    }

    // ---------------- gmax ----------------
    float lmax = -3.0e38f;
    #pragma unroll
    for (int n = 0; n < 8; n++) {
        if (v0) lmax = fmaxf(lmax, fmaxf(acc[n][0], acc[n][1]));
        if (v1) lmax = fmaxf(lmax, fmaxf(acc[n][2], acc[n][3]));
    }
    #pragma unroll
    for (int off = 16; off; off >>= 1)
        lmax = fmaxf(lmax, __shfl_xor_sync(0xffffffffu, lmax, off));
    if (lane == 0) red[wid] = lmax;
    __syncthreads();   // all warps past GEMM -> Ef alias over B tiles now safe
    if (tid == 0) {
        float g = red[0];
        #pragma unroll
        for (int w2 = 1; w2 < 8; w2++) g = fmaxf(g, red[w2]);
        red[8] = g * (1.0f / 64.0f);
    }
    __syncthreads();
    const float gmax = red[8];

    // ---------------- exp, Ef stores, invCol ----------------
    {
        const float inv64 = 1.0f / 64.0f;
        float sa = 0.0f, sbm = 0.0f;
        #pragma unroll
        for (int n = 0; n < 8; n++) {
            int c = 8 * n + 2 * c2;
            if (v0) {
                float e0 = __expf(fmaf(acc[n][0], inv64, -gmax));
                float e1 = __expf(fmaf(acc[n][1], inv64, -gmax));
                *reinterpret_cast<float2*>(&Ef[r0 * SE + c]) = make_float2(e0, e1);
                sa += e0 + e1;
            }
            if (v1) {
                float e2 = __expf(fmaf(acc[n][2], inv64, -gmax));
                float e3 = __expf(fmaf(acc[n][3], inv64, -gmax));
                *reinterpret_cast<float2*>(&Ef[(r0 + 8) * SE + c]) = make_float2(e2, e3);
                sbm += e2 + e3;
            }
        }
        sa  += __shfl_xor_sync(0xffffffffu, sa, 1);
        sa  += __shfl_xor_sync(0xffffffffu, sa, 2);
        sbm += __shfl_xor_sync(0xffffffffu, sbm, 1);
        sbm += __shfl_xor_sync(0xffffffffu, sbm, 2);
        if (c2 == 0) {
            if (v0) invCol[r0] = 1.0f / sa;
            if (v1) invCol[r0 + 8] = 1.0f / sbm;
        }
    }
    __syncthreads();

    // invRow[l] = 1 / sum_{r<100} Ef[r][l]
    if (tid < 64) {
        float s = 0.0f;
        #pragma unroll 4
        for (int rr = 0; rr < 100; rr++) s += Ef[rr * SE + tid];
        invRow[tid] = 1.0f / s;
    }
    __syncthreads();

    // ---------------- sm output + argmax (first-index tie-break) ----------------
    float best = -1.0f;
    int   bidx = 0;
    float* smo = out_sm + (size_t)m * 4096;
    #pragma unroll
    for (int f = tid; f < 4096; f += TPB) {
        int l = f >> 6, k = f & 63;
        int rr = 11 + ((k >> 3) * 10) + (k & 7);  // inner crop of 10x10
        float e = Ef[rr * SE + l];
        float v = e * e * invRow[l] * invCol[rr];
        smo[f] = v;
        if (v > best) { best = v; bidx = f; }
    }
    #pragma unroll
    for (int off = 16; off; off >>= 1) {
        float ov = __shfl_xor_sync(0xffffffffu, best, off);
        int   oi = __shfl_xor_sync(0xffffffffu, bidx, off);
        if (ov > best || (ov == best && oi < bidx)) { best = ov; bidx = oi; }
    }
    if (lane == 0) {
        red[wid] = best;
        ired[8 + wid] = bidx;
    }
    __syncthreads();
    if (tid == 0) {
        float bv = red[0];
        int   bi = ired[8];
        #pragma unroll
        for (int w2 = 1; w2 < 8; w2++) {
            float ov = red[w2];
            int   oi = ired[8 + w2];
            if (ov > bv || (ov == bv && oi < bi)) { bv = ov; bi = oi; }
        }
        ired[16] = bi;
    }
    __syncthreads();
    const int idx = ired[16];

    // ---------------- epilogue: lazy conf_ff window + softmax + keypoints ----------------
    if (tid < 32) {
        const int idx_l = idx >> 6;
        const int idx_r = idx & 63;
        const float scl = (float)(*hw0i) / (float)(*hw0f);
        const float rs8 = 0.35355339059327376f;  // 1/sqrt(8)

        const int  di = tid / 3;
        const int  dj = tid - di * 3;
        const bool vv = tid < 9;

        float w = -3.0e38f;
        if (vv) {
            int wi = (idx_r >> 3) + di - 1; if (wi < 0) wi += 10;
            int wj = (idx_r & 7)  + dj - 1; if (wj < 0) wj += 10;
            int wr = wi * 10 + wj;
            float dot = 0.0f;
            #pragma unroll
            for (int c = 0; c < 8; c++)
                dot = fmaf(Aff[c * SAF + idx_l], Bff[c * SBF + wr], dot);
            w = dot * rs8;
        }
        float mx = w;
        #pragma unroll
        for (int off = 16; off; off >>= 1)
            mx = fmaxf(mx, __shfl_xor_sync(0xffffffffu, mx, off));
        float t = vv ? __expf((w - mx) * 0.1f) : 0.0f;   // TEMP = 10
        float s = t;
        #pragma unroll
        for (int off = 16; off; off >>= 1)
            s += __shfl_xor_sync(0xffffffffu, s, off);
        float pr = t / s;
        if (vv) out_probs[(size_t)m * 9 + tid] = pr;

        float cx = vv ? pr * (float)(dj - 1) : 0.0f;
        float cy = vv ? pr * (float)(di - 1) : 0.0f;
        #pragma unroll
        for (int off = 16; off; off >>= 1) {
            cx += __shfl_xor_sync(0xffffffffu, cx, off);
            cy += __shfl_xor_sync(0xffffffffu, cy, off);
        }
        if (tid == 0) {
            float m0x = mk0c[2 * m], m0y = mk0c[2 * m + 1];
            float m1x = mk1c[2 * m], m1y = mk1c[2 * m + 1];
            out_mk0[2 * m]     = fmaf((float)(idx_l & 7) - 3.5f, scl, m0x);
            out_mk0[2 * m + 1] = fmaf((float)(idx_l >> 3) - 3.5f, scl, m0y);
            out_mk1[2 * m]     = m1x + ((float)(idx_r & 7) - 3.5f) * scl + cx * scl;
            out_mk1[2 * m + 1] = m1y + ((float)(idx_r >> 3) - 3.5f) * scl + cy * scl;
        }
    }
}

extern "C" void kernel_launch(void* const* d_in, const int* in_sizes, int n_in,
                              void* d_out, int out_size) {
    const float* feat0 = (const float*)d_in[0];
    const float* feat1 = (const float*)d_in[1];
    const float* mk0c  = (const float*)d_in[2];
    const float* mk1c  = (const float*)d_in[3];
    // d_in[4] = mconf (unused), d_in[5] = b_ids (unused)
    const int* hw0i = (const int*)d_in[6];
    const int* hw0f = (const int*)d_in[7];

    const int M = in_sizes[0] / 4096;

    float* out       = (float*)d_out;
    float* out_mk0   = out;
    float* out_mk1   = out + (size_t)2 * M;
    float* out_probs = out + (size_t)4 * M;
    float* out_sm    = out + (size_t)13 * M;

    cudaFuncSetAttribute(fine_matching_kernel,
                         cudaFuncAttributeMaxDynamicSharedMemorySize, SMEM_BYTES);
    fine_matching_kernel<<<M, TPB, SMEM_BYTES>>>(
        feat0, feat1, mk0c, mk1c, hw0i, hw0f,
        out_mk0, out_mk1, out_probs, out_sm);
}

// round 7
// speedup vs baseline: 1.1478x; 1.0130x over previous
#include <cuda_runtime.h>
#include <cuda_bf16.h>
#include <stdint.h>

// FineMatching R7: R6 + critical-path cuts:
//  - no softmax stabilization (conf values are tiny; shift cancels exactly)
//  - Ef in its own smem region (no alias barrier after GEMM)
//  - invRow column sums via warp shfl butterflies instead of 100-iter loop

#define TPB 256
#define SE 66     // Ef stride [r][l] floats
#define SAF 68    // Aff stride floats
#define SBF 113   // Bff stride floats
#define SCP 68    // colpart stride floats
#define BSTR 144  // feat0 bf16 tile row stride bytes (72 b16)

// byte offsets in dynamic smem
#define B_AFF   0        // 8*68*4  = 2176   (feat0 ch 56..63, [c][l])
#define B_BFF   2176     // 8*113*4 = 3616   (feat1 ch 56..63, [c][r])
#define B_BHI   5792     // feat0 hi bf16 [64 l][72], 9216
#define B_BLO   15008    // feat0 lo bf16, 9216 -> 24224
#define B_EF    24224    // Ef [100][66] f32 = 26400 -> 50624 (own region, no alias)
#define B_CP    50624    // colpart [7][68] f32 = 1904 -> 52528
#define B_IROW  52528    // 64 f32
#define B_ICOL  52784    // 100 f32
#define B_RED   53184    // 20 f32 (floats 0..7 best, ints 8..15 idx, ired[16] final)
#define SMEM_BYTES 53264 // x3 CTAs = 159.8KB

__device__ __forceinline__ uint32_t smem_u32(const void* p) {
    uint32_t a;
    asm("{ .reg .u64 t; cvta.to.shared.u64 t, %1; cvt.u32.u64 %0, t; }"
        : "=r"(a) : "l"(p));
    return a;
}
__device__ __forceinline__ void ldm4(uint32_t addr, uint32_t* r) {
    asm volatile("ldmatrix.sync.aligned.m8n8.x4.shared.b16 {%0,%1,%2,%3}, [%4];"
                 : "=r"(r[0]), "=r"(r[1]), "=r"(r[2]), "=r"(r[3]) : "r"(addr));
}
__device__ __forceinline__ void mma16816(float* d, const uint32_t* a, uint32_t b0, uint32_t b1) {
    asm volatile("mma.sync.aligned.m16n8k16.row.col.f32.bf16.bf16.f32 "
                 "{%0,%1,%2,%3}, {%4,%5,%6,%7}, {%8,%9}, {%0,%1,%2,%3};"
                 : "+f"(d[0]), "+f"(d[1]), "+f"(d[2]), "+f"(d[3])
                 : "r"(a[0]), "r"(a[1]), "r"(a[2]), "r"(a[3]), "r"(b0), "r"(b1));
}
__device__ __forceinline__ uint32_t pack_bf2(__nv_bfloat16 a, __nv_bfloat16 b) {
    __nv_bfloat162 t = __halves2bfloat162(a, b);
    return *reinterpret_cast<uint32_t*>(&t);
}
__device__ __forceinline__ void split2(float x, float y, uint32_t& hi, uint32_t& lo) {
    __nv_bfloat16 hx = __float2bfloat16(x), hy = __float2bfloat16(y);
    __nv_bfloat16 lx = __float2bfloat16(x - __bfloat162float(hx));
    __nv_bfloat16 ly = __float2bfloat16(y - __bfloat162float(hy));
    hi = pack_bf2(hx, hy);
    lo = pack_bf2(lx, ly);
}

__global__ __launch_bounds__(TPB, 3)
void fine_matching_kernel(const float* __restrict__ feat0,
                          const float* __restrict__ feat1,
                          const float* __restrict__ mk0c,
                          const float* __restrict__ mk1c,
                          const int*   __restrict__ hw0i,
                          const int*   __restrict__ hw0f,
                          float* __restrict__ out_mk0,
                          float* __restrict__ out_mk1,
                          float* __restrict__ out_probs,
                          float* __restrict__ out_sm)
{
    extern __shared__ float smem[];
    uint8_t* smb = reinterpret_cast<uint8_t*>(smem);
    const uint32_t sb = smem_u32(smem);

    float* Ef      = reinterpret_cast<float*>(smb + B_EF);
    float* Aff     = reinterpret_cast<float*>(smb + B_AFF);
    float* Bff     = reinterpret_cast<float*>(smb + B_BFF);
    float* colpart = reinterpret_cast<float*>(smb + B_CP);
    float* invRow  = reinterpret_cast<float*>(smb + B_IROW);
    float* invCol  = reinterpret_cast<float*>(smb + B_ICOL);
    float* red     = reinterpret_cast<float*>(smb + B_RED);
    int*   ired    = reinterpret_cast<int*>(red);

    const int m    = blockIdx.x;
    const int tid  = threadIdx.x;
    const int wid  = tid >> 5;
    const int lane = tid & 31;
    const int q    = lane >> 2;
    const int c2   = lane & 3;

    // ---------------- stage feat0 -> bf16 hi/lo tiles (+ Aff ch 56..63) ----------------
    {
        const float4* f0 = reinterpret_cast<const float4*>(feat0 + (size_t)m * 4096);
        #pragma unroll 2
        for (int idx = tid; idx < 1024; idx += TPB) {
            float4 v = f0[idx];
            int l = idx >> 4, c4 = (idx & 15) << 2;
            uint32_t off = (uint32_t)l * BSTR + c4 * 2;
            if (c4 < 56) {
                uint32_t h01, l01, h23, l23;
                split2(v.x, v.y, h01, l01);
                split2(v.z, v.w, h23, l23);
                *reinterpret_cast<uint2*>(smb + B_BHI + off) = make_uint2(h01, h23);
                *reinterpret_cast<uint2*>(smb + B_BLO + off) = make_uint2(l01, l23);
            } else {
                *reinterpret_cast<uint2*>(smb + B_BHI + off) = make_uint2(0u, 0u);
                *reinterpret_cast<uint2*>(smb + B_BLO + off) = make_uint2(0u, 0u);
                int c = c4 - 56;
                Aff[(c + 0) * SAF + l] = v.x;
                Aff[(c + 1) * SAF + l] = v.y;
                Aff[(c + 2) * SAF + l] = v.z;
                Aff[(c + 3) * SAF + l] = v.w;
            }
        }
    }

    // ---------------- preload feat1 fragments gmem->regs (warps 0..6), harvest Bff ----------------
    const int  r0 = 16 * wid + q;      // warp's A rows: r0, r0+8
    const bool v0 = (wid < 7) && (r0 < 100);
    const bool v1 = (wid < 7) && (r0 + 8 < 100);
    float2 af[4][4];
    if (wid < 7) {
        const float* A = feat1 + (size_t)m * 6400;
        const float2 z = make_float2(0.0f, 0.0f);
        #pragma unroll
        for (int ks = 0; ks < 4; ks++) {
            int k0 = 16 * ks + 2 * c2;
            af[ks][0] = v0 ? *reinterpret_cast<const float2*>(A + r0 * 64 + k0) : z;
            af[ks][1] = v1 ? *reinterpret_cast<const float2*>(A + (r0 + 8) * 64 + k0) : z;
            if (ks < 3) {
                af[ks][2] = v0 ? *reinterpret_cast<const float2*>(A + r0 * 64 + k0 + 8) : z;
                af[ks][3] = v1 ? *reinterpret_cast<const float2*>(A + (r0 + 8) * 64 + k0 + 8) : z;
            } else {
                af[ks][2] = z;
                af[ks][3] = z;
            }
        }
        // ff channels 56+2c2, 57+2c2 of rows r0, r0+8 -> Bff
        float2 w0 = v0 ? *reinterpret_cast<const float2*>(A + r0 * 64 + 56 + 2 * c2) : z;
        float2 w1 = v1 ? *reinterpret_cast<const float2*>(A + (r0 + 8) * 64 + 56 + 2 * c2) : z;
        if (v0) {
            Bff[(2 * c2 + 0) * SBF + r0] = w0.x;
            Bff[(2 * c2 + 1) * SBF + r0] = w0.y;
        }
        if (v1) {
            Bff[(2 * c2 + 0) * SBF + r0 + 8] = w1.x;
            Bff[(2 * c2 + 1) * SBF + r0 + 8] = w1.y;
        }
    }
    __syncthreads();

    // ---------------- GEMM: 3 bf16 terms (hh + hl + lh) fused per k-step ----------------
    float acc[8][4];
    #pragma unroll
    for (int n = 0; n < 8; n++)
        #pragma unroll
        for (int p = 0; p < 4; p++) acc[n][p] = 0.0f;

    if (wid < 7) {
        const uint32_t bLane = (uint32_t)((((lane >> 4) & 1) * 8 + (lane & 7)) * BSTR)
                             + (uint32_t)(((lane >> 3) & 1) * 16);
        const uint32_t Bh = sb + B_BHI + bLane;
        const uint32_t Bl = sb + B_BLO + bLane;
        #pragma unroll
        for (int ks = 0; ks < 4; ks++) {
            uint32_t ah[4], al[4];
            #pragma unroll
            for (int i = 0; i < 4; i++)
                split2(af[ks][i].x, af[ks][i].y, ah[i], al[i]);
            #pragma unroll
            for (int j2 = 0; j2 < 4; j2++) {
                uint32_t bh[4], bl[4];
                ldm4(Bh + j2 * 16 * BSTR + ks * 32, bh);
                ldm4(Bl + j2 * 16 * BSTR + ks * 32, bl);
                mma16816(acc[2 * j2],     ah, bh[0], bh[1]);
                mma16816(acc[2 * j2 + 1], ah, bh[2], bh[3]);
                mma16816(acc[2 * j2],     ah, bl[0], bl[1]);
                mma16816(acc[2 * j2 + 1], ah, bl[2], bl[3]);
                mma16816(acc[2 * j2],     al, bh[0], bh[1]);
                mma16816(acc[2 * j2 + 1], al, bh[2], bh[3]);
            }
        }
    }

    // ---------------- exp (no stabilization: |conf| < ~2), Ef stores, row sums, col partials ----------------
    // Softmax shift cancels exactly in sm = softmax_r * softmax_l, so exp(conf) directly is exact math.
    {
        const float inv64 = 1.0f / 64.0f;
        float sa = 0.0f, sbm = 0.0f;
        float t0[8], t1[8];
        #pragma unroll
        for (int n = 0; n < 8; n++) {
            float e0 = 0.0f, e1 = 0.0f, e2 = 0.0f, e3 = 0.0f;
            int c = 8 * n + 2 * c2;
            if (v0) {
                e0 = __expf(acc[n][0] * inv64);
                e1 = __expf(acc[n][1] * inv64);
                *reinterpret_cast<float2*>(&Ef[r0 * SE + c]) = make_float2(e0, e1);
                sa += e0 + e1;
            }
            if (v1) {
                e2 = __expf(acc[n][2] * inv64);
                e3 = __expf(acc[n][3] * inv64);
                *reinterpret_cast<float2*>(&Ef[(r0 + 8) * SE + c]) = make_float2(e2, e3);
                sbm += e2 + e3;
            }
            t0[n] = e0 + e2;
            t1[n] = e1 + e3;
        }
        // row sums (over l) -> invCol
        sa  += __shfl_xor_sync(0xffffffffu, sa, 1);
        sa  += __shfl_xor_sync(0xffffffffu, sa, 2);
        sbm += __shfl_xor_sync(0xffffffffu, sbm, 1);
        sbm += __shfl_xor_sync(0xffffffffu, sbm, 2);
        if (c2 == 0) {
            if (v0) invCol[r0] = 1.0f / sa;
            if (v1) invCol[r0 + 8] = 1.0f / sbm;
        }
        // column partial sums over this warp's 16 rows: butterfly over q (offsets 4, 8, 16)
        if (wid < 7) {
            #pragma unroll
            for (int off = 4; off <= 16; off <<= 1) {
                #pragma unroll
                for (int n = 0; n < 8; n++) {
                    t0[n] += __shfl_xor_sync(0xffffffffu, t0[n], off);
                    t1[n] += __shfl_xor_sync(0xffffffffu, t1[n], off);
                }
            }
            if (q == 0) {
                #pragma unroll
                for (int n = 0; n < 8; n++)
                    *reinterpret_cast<float2*>(&colpart[wid * SCP + 8 * n + 2 * c2]) =
                        make_float2(t0[n], t1[n]);
            }
        }
    }
    __syncthreads();

    // invRow[l] = 1 / sum of 7 warp partials
    if (tid < 64) {
        float s = 0.0f;
        #pragma unroll
        for (int w2 = 0; w2 < 7; w2++) s += colpart[w2 * SCP + tid];
        invRow[tid] = 1.0f / s;
    }
    __syncthreads();

    // ---------------- sm output + argmax (first-index tie-break) ----------------
    float best = -1.0f;
    int   bidx = 0;
    float* smo = out_sm + (size_t)m * 4096;
    #pragma unroll
    for (int f = tid; f < 4096; f += TPB) {
        int l = f >> 6, k = f & 63;
        int rr = 11 + ((k >> 3) * 10) + (k & 7);  // inner crop of 10x10
        float e = Ef[rr * SE + l];
        float v = e * e * invRow[l] * invCol[rr];
        smo[f] = v;
        if (v > best) { best = v; bidx = f; }
    }
    #pragma unroll
    for (int off = 16; off; off >>= 1) {
        float ov = __shfl_xor_sync(0xffffffffu, best, off);
        int   oi = __shfl_xor_sync(0xffffffffu, bidx, off);
        if (ov > best || (ov == best && oi < bidx)) { best = ov; bidx = oi; }
    }
    if (lane == 0) {
        red[wid] = best;
        ired[8 + wid] = bidx;
    }
    __syncthreads();
    if (tid == 0) {
        float bv = red[0];
        int   bi = ired[8];
        #pragma unroll
        for (int w2 = 1; w2 < 8; w2++) {
            float ov = red[w2];
            int   oi = ired[8 + w2];
            if (ov > bv || (ov == bv && oi < bi)) { bv = ov; bi = oi; }
        }
        ired[16] = bi;
    }
    __syncthreads();
    const int idx = ired[16];

    // ---------------- epilogue: lazy conf_ff window + softmax + keypoints ----------------
    if (tid < 32) {
        const int idx_l = idx >> 6;
        const int idx_r = idx & 63;
        const float scl = (float)(*hw0i) / (float)(*hw0f);
        const float rs8 = 0.35355339059327376f;  // 1/sqrt(8)

        const int  di = tid / 3;
        const int  dj = tid - di * 3;
        const bool vv = tid < 9;

        float w = -3.0e38f;
        if (vv) {
            int wi = (idx_r >> 3) + di - 1; if (wi < 0) wi += 10;
            int wj = (idx_r & 7)  + dj - 1; if (wj < 0) wj += 10;
            int wr = wi * 10 + wj;
            float dot = 0.0f;
            #pragma unroll
            for (int c = 0; c < 8; c++)
                dot = fmaf(Aff[c * SAF + idx_l], Bff[c * SBF + wr], dot);
            w = dot * rs8;
        }
        float mx = w;
        #pragma unroll
        for (int off = 16; off; off >>= 1)
            mx = fmaxf(mx, __shfl_xor_sync(0xffffffffu, mx, off));
        float t = vv ? __expf((w - mx) * 0.1f) : 0.0f;   // TEMP = 10
        float s = t;
        #pragma unroll
        for (int off = 16; off; off >>= 1)
            s += __shfl_xor_sync(0xffffffffu, s, off);
        float pr = t / s;
        if (vv) out_probs[(size_t)m * 9 + tid] = pr;

        float cx = vv ? pr * (float)(dj - 1) : 0.0f;
        float cy = vv ? pr * (float)(di - 1) : 0.0f;
        #pragma unroll
        for (int off = 16; off; off >>= 1) {
            cx += __shfl_xor_sync(0xffffffffu, cx, off);
            cy += __shfl_xor_sync(0xffffffffu, cy, off);
        }
        if (tid == 0) {
            float m0x = mk0c[2 * m], m0y = mk0c[2 * m + 1];
            float m1x = mk1c[2 * m], m1y = mk1c[2 * m + 1];
            out_mk0[2 * m]     = fmaf((float)(idx_l & 7) - 3.5f, scl, m0x);
            out_mk0[2 * m + 1] = fmaf((float)(idx_l >> 3) - 3.5f, scl, m0y);
            out_mk1[2 * m]     = m1x + ((float)(idx_r & 7) - 3.5f) * scl + cx * scl;
            out_mk1[2 * m + 1] = m1y + ((float)(idx_r >> 3) - 3.5f) * scl + cy * scl;
        }
    }
}

extern "C" void kernel_launch(void* const* d_in, const int* in_sizes, int n_in,
                              void* d_out, int out_size) {
    const float* feat0 = (const float*)d_in[0];
    const float* feat1 = (const float*)d_in[1];
    const float* mk0c  = (const float*)d_in[2];
    const float* mk1c  = (const float*)d_in[3];
    // d_in[4] = mconf (unused), d_in[5] = b_ids (unused)
    const int* hw0i = (const int*)d_in[6];
    const int* hw0f = (const int*)d_in[7];

    const int M = in_sizes[0] / 4096;

    float* out       = (float*)d_out;
    float* out_mk0   = out;
    float* out_mk1   = out + (size_t)2 * M;
    float* out_probs = out + (size_t)4 * M;
    float* out_sm    = out + (size_t)13 * M;

    cudaFuncSetAttribute(fine_matching_kernel,
                         cudaFuncAttributeMaxDynamicSharedMemorySize, SMEM_BYTES);
    fine_matching_kernel<<<M, TPB, SMEM_BYTES>>>(
        feat0, feat1, mk0c, mk1c, hw0i, hw0f,
        out_mk0, out_mk1, out_probs, out_sm);
}